// round 4
// baseline (speedup 1.0000x reference)
#include <cuda_runtime.h>

#define BB 4
#define CC 84
#define CP 80          // channels in the max (points[:, :-4])
#define HH 512
#define WW 512
#define HW (HH * WW)

#define TR 8           // interior tile rows
#define TC 32          // interior tile cols
#define PRr (TR + 2)   // 10
#define PCc (TC + 2)   // 34
#define NT (TR * TC)   // 256 threads
#define NHALO (2 * PCc + 2 * TR)  // 84 halo positions

// channel-max over CP channels at one global position (0 if out of bounds)
__device__ __forceinline__ float probs_at(const float* __restrict__ pts,
                                          int b, int gh, int gw) {
    if (gh < 0 || gh >= HH || gw < 0 || gw >= WW) return 0.0f;
    const float* base = pts + ((size_t)b * CC) * HW + (size_t)gh * WW + gw;
    float m0 = -3.402823466e38f, m1 = -3.402823466e38f;
    #pragma unroll 10
    for (int c = 0; c < CP; c += 2) {
        m0 = fmaxf(m0, base[(size_t)c * HW]);
        m1 = fmaxf(m1, base[(size_t)(c + 1) * HW]);
    }
    return fmaxf(m0, m1);
}

// ---------------------------------------------------------------------------
// Fused: channel-max -> 3x3 NMS (SMEM probs tile w/ halo) -> apply & write.
// Phase-3 re-reads rely on L2 residency of phase-1 reads (no SMEM cache).
// grid (WW/TC, HH/TR, BB), block 256, smem 1.4 KB -> high occupancy.
// ---------------------------------------------------------------------------
__global__ void __launch_bounds__(NT, 6)
fused_nms_kernel(const float* __restrict__ pts, float* __restrict__ out) {
    __shared__ float s_pr[PRr * PCc];

    const int tid = threadIdx.x;
    const int bx = blockIdx.x, by = blockIdx.y, b = blockIdx.z;
    const int r  = tid >> 5;                 // 0..7
    const int cc = tid & 31;                 // 0..31
    const int gh = by * TR + r;
    const int gw = bx * TC + cc;

    // Phase 1a: interior probs (own pixel). Reads allocate in L2 (reused in P3).
    s_pr[(r + 1) * PCc + (cc + 1)] = probs_at(pts, b, gh, gw);

    // Phase 1b: 84 halo positions, threads 0..83 (mostly L2 hits from neighbors).
    if (tid < NHALO) {
        int pr, pc;
        if (tid < PCc)            { pr = 0;               pc = tid; }
        else if (tid < 2 * PCc)   { pr = PRr - 1;         pc = tid - PCc; }
        else if (tid < 2 * PCc + TR) { pr = 1 + (tid - 2 * PCc);      pc = 0; }
        else                      { pr = 1 + (tid - 2 * PCc - TR);    pc = PCc - 1; }
        s_pr[pr * PCc + pc] =
            probs_at(pts, b, by * TR + pr - 1, bx * TC + pc - 1);
    }

    __syncthreads();

    // Phase 2: 3x3 NMS mask. Before center: strict > ; after: >=
    const int pr = r + 1, pc = cc + 1;
    const float* P = s_pr;
    float cen = P[pr * PCc + pc];
    bool ok = (cen >  P[(pr - 1) * PCc + (pc - 1)]) &
              (cen >  P[(pr - 1) * PCc +  pc     ]) &
              (cen >  P[(pr - 1) * PCc + (pc + 1)]) &
              (cen >  P[ pr      * PCc + (pc - 1)]) &
              (cen >= P[ pr      * PCc + (pc + 1)]) &
              (cen >= P[(pr + 1) * PCc + (pc - 1)]) &
              (cen >= P[(pr + 1) * PCc +  pc     ]) &
              (cen >= P[(pr + 1) * PCc + (pc + 1)]);
    float f = ok ? 1.0f : 0.0f;

    // Phase 3: re-read all 84 channels (L2-hot for c<80), scale, stream out.
    const size_t pixoff = ((size_t)b * CC) * HW + (size_t)gh * WW + gw;
    const float* src = pts + pixoff;
    float*       dst = out + pixoff;
    #pragma unroll 4
    for (int c = 0; c < CC; ++c) {
        float v = __ldcs(src + (size_t)c * HW);   // evict-first: dead after this
        __stwt(dst + (size_t)c * HW, f * v);      // streaming store: no L2 pollution
    }
}

// ---------------------------------------------------------------------------
extern "C" void kernel_launch(void* const* d_in, const int* in_sizes, int n_in,
                              void* d_out, int out_size) {
    const float* pts = (const float*)d_in[0];
    float*       out = (float*)d_out;

    dim3 grid(WW / TC, HH / TR, BB);   // (16, 64, 4) = 4096 CTAs
    fused_nms_kernel<<<grid, NT>>>(pts, out);
}

// round 6
// speedup vs baseline: 1.0092x; 1.0092x over previous
#include <cuda_runtime.h>
#include <cfloat>

#define BB 4
#define CC 84
#define CP 80          // channels in the max (points[:, :-4])
#define HH 512
#define WW 512
#define HW (HH * WW)

#define TR 8           // interior tile rows
#define TC 32          // interior tile cols
#define PRr (TR + 2)   // 10
#define PCc (TC + 2)   // 34
#define NP (PRr * PCc) // 340 padded positions
#define NT 256         // threads per CTA

// ---------------------------------------------------------------------------
// Fused: channel-max (coalesced padded-tile, register accum) -> 3x3 NMS
// (SMEM probs) -> apply & write (L2-hot re-read).
// grid (WW/TC, HH/TR, BB) = (16, 64, 4), block 256.
// ---------------------------------------------------------------------------
__global__ void __launch_bounds__(NT, 8)
fused_nms_kernel(const float* __restrict__ pts, float* __restrict__ out) {
    __shared__ float s_pr[NP];

    const int tid = threadIdx.x;
    const int bx = blockIdx.x, by = blockIdx.y, b = blockIdx.z;
    const size_t bbase = (size_t)b * CC * HW;

    // ---- Phase 1: padded-tile probs, all loads coalesced row segments ----
    // Position 0: p0 = tid (always active, 256 < 340).
    int pr0 = tid / PCc, pc0 = tid - pr0 * PCc;
    int gh0 = by * TR + pr0 - 1, gw0 = bx * TC + pc0 - 1;
    bool in0 = (gh0 >= 0) & (gh0 < HH) & (gw0 >= 0) & (gw0 < WW);
    const float* base0 = pts + bbase + (size_t)(in0 ? gh0 : 0) * WW + (in0 ? gw0 : 0);

    // Position 1: p1 = tid + 256, active for tid < 84.
    int p1 = tid + NT;
    bool act1 = p1 < NP;
    int pr1 = act1 ? (p1 / PCc) : 0, pc1 = act1 ? (p1 - (p1 / PCc) * PCc) : 0;
    int gh1 = by * TR + pr1 - 1, gw1 = bx * TC + pc1 - 1;
    bool in1 = act1 & (gh1 >= 0) & (gh1 < HH) & (gw1 >= 0) & (gw1 < WW);
    const float* base1 = pts + bbase + (size_t)(in1 ? gh1 : 0) * WW + (in1 ? gw1 : 0);

    float m0 = -FLT_MAX, m1 = -FLT_MAX;
    #pragma unroll 8
    for (int c = 0; c < CP; ++c) {
        m0 = fmaxf(m0, base0[(size_t)c * HW]);
        m1 = fmaxf(m1, base1[(size_t)c * HW]);   // broadcast/harmless if inactive
    }
    s_pr[tid] = in0 ? m0 : 0.0f;                 // zero-padding outside image
    if (act1) s_pr[p1] = in1 ? m1 : 0.0f;

    __syncthreads();

    // ---- Phase 2: 3x3 NMS mask. Before center: strict > ; after: >= ----
    const int r  = tid >> 5;                     // 0..7
    const int cc = tid & 31;                     // 0..31
    const int pp = (r + 1) * PCc + (cc + 1);
    float cen = s_pr[pp];
    bool ok = (cen >  s_pr[pp - PCc - 1]) &
              (cen >  s_pr[pp - PCc    ]) &
              (cen >  s_pr[pp - PCc + 1]) &
              (cen >  s_pr[pp - 1      ]) &
              (cen >= s_pr[pp + 1      ]) &
              (cen >= s_pr[pp + PCc - 1]) &
              (cen >= s_pr[pp + PCc    ]) &
              (cen >= s_pr[pp + PCc + 1]);
    float f = ok ? 1.0f : 0.0f;

    // ---- Phase 3: re-read 84 channels (L2-hot for c<80), scale, stream out ----
    const int gh = by * TR + r, gw = bx * TC + cc;
    const size_t pixoff = bbase + (size_t)gh * WW + gw;
    const float* src = pts + pixoff;
    float*       dst = out + pixoff;
    #pragma unroll 4
    for (int c = 0; c < CC; ++c) {
        float v = __ldcs(src + (size_t)c * HW);  // evict-first: dead after this
        __stcs(dst + (size_t)c * HW, f * v);     // streaming store
    }
}

// ---------------------------------------------------------------------------
extern "C" void kernel_launch(void* const* d_in, const int* in_sizes, int n_in,
                              void* d_out, int out_size) {
    const float* pts = (const float*)d_in[0];
    float*       out = (float*)d_out;

    dim3 grid(WW / TC, HH / TR, BB);   // (16, 64, 4)
    fused_nms_kernel<<<grid, NT>>>(pts, out);
}

// round 10
// speedup vs baseline: 1.0350x; 1.0256x over previous
#include <cuda_runtime.h>
#include <cfloat>

#define BB 4
#define CC 84
#define CP 80          // channels in the max (points[:, :-4])
#define HH 512
#define WW 512
#define HW (HH * WW)

#define TR 8           // interior tile rows
#define TC 64          // interior tile cols (32 float2 per row)
#define PRr (TR + 2)   // 10
#define PC2 34         // padded float2 cols: covers gw offsets -2..65
#define NP (PRr * PC2) // 340 padded float2 positions
#define NT 256         // threads per CTA
#define SCOLS 68       // smem probs cols (gw offsets -2..65)

// ---------------------------------------------------------------------------
// Fused, float2-vectorized: channel-max (coalesced padded tile) -> 3x3 NMS
// (SMEM probs) -> apply & write (phase-1 reads are L2-hot at re-read time;
// 4 CTAs/SM keeps chip-wide reuse window ~102 MB < L2).
// grid (WW/TC, HH/TR, BB) = (8, 64, 4), block 256.
// ---------------------------------------------------------------------------
__global__ void __launch_bounds__(NT, 4)
fused_nms_kernel(const float2* __restrict__ pts2, float2* __restrict__ out2) {
    __shared__ float s_pr[PRr * SCOLS];

    const int tid = threadIdx.x;
    const int bx = blockIdx.x, by = blockIdx.y, b = blockIdx.z;
    const size_t bbase2 = (size_t)b * CC * (HW / 2);     // float2 index base

    // ---- Phase 1: padded-tile probs, float2 loads, coalesced row segments ----
    // Position 0: p0 = tid (always active). Position 1: tid+256 (tid<84).
    int pr0 = tid / PC2, pc0 = tid - pr0 * PC2;
    int gh0 = by * TR + pr0 - 1;
    int gx0 = bx * (TC / 2) + pc0 - 1;                   // float2 col index
    bool in0 = (gh0 >= 0) & (gh0 < HH) & (gx0 >= 0) & (gx0 < WW / 2);
    const float2* base0 = pts2 + bbase2
        + (size_t)(in0 ? gh0 : 0) * (WW / 2) + (in0 ? gx0 : 0);

    int p1 = tid + NT;
    bool act1 = p1 < NP;
    int pr1 = p1 / PC2, pc1 = p1 - pr1 * PC2;
    int gh1 = by * TR + pr1 - 1;
    int gx1 = bx * (TC / 2) + pc1 - 1;
    bool in1 = act1 & (gh1 >= 0) & (gh1 < HH) & (gx1 >= 0) & (gx1 < WW / 2);
    const float2* base1 = pts2 + bbase2
        + (size_t)(in1 ? gh1 : 0) * (WW / 2) + (in1 ? gx1 : 0);

    float2 m0 = make_float2(-FLT_MAX, -FLT_MAX);
    float2 m1 = m0;
    #pragma unroll 8
    for (int c = 0; c < CP; ++c) {
        float2 v0 = base0[(size_t)c * (HW / 2)];
        float2 v1 = base1[(size_t)c * (HW / 2)];
        m0.x = fmaxf(m0.x, v0.x);  m0.y = fmaxf(m0.y, v0.y);
        m1.x = fmaxf(m1.x, v1.x);  m1.y = fmaxf(m1.y, v1.y);
    }
    // write probs (zero outside image)
    s_pr[pr0 * SCOLS + pc0 * 2 + 0] = in0 ? m0.x : 0.0f;
    s_pr[pr0 * SCOLS + pc0 * 2 + 1] = in0 ? m0.y : 0.0f;
    if (act1) {
        s_pr[pr1 * SCOLS + pc1 * 2 + 0] = in1 ? m1.x : 0.0f;
        s_pr[pr1 * SCOLS + pc1 * 2 + 1] = in1 ? m1.y : 0.0f;
    }

    __syncthreads();

    // ---- Phase 2: 3x3 NMS mask for this thread's 2 pixels ----
    // neighbors before center: strict > ; after center: >=
    const int r    = tid >> 5;            // 0..7
    const int lane = tid & 31;            // 0..31
    const int cc   = lane * 2;            // first of this thread's 2 pixel cols
    float2 f;
    #pragma unroll
    for (int j = 0; j < 2; ++j) {
        const int sp = (r + 1) * SCOLS + (cc + j + 2);   // smem col = gw_off + 2
        float cen = s_pr[sp];
        bool ok = (cen >  s_pr[sp - SCOLS - 1]) &
                  (cen >  s_pr[sp - SCOLS    ]) &
                  (cen >  s_pr[sp - SCOLS + 1]) &
                  (cen >  s_pr[sp - 1        ]) &
                  (cen >= s_pr[sp + 1        ]) &
                  (cen >= s_pr[sp + SCOLS - 1]) &
                  (cen >= s_pr[sp + SCOLS    ]) &
                  (cen >= s_pr[sp + SCOLS + 1]);
        (j == 0 ? f.x : f.y) = ok ? 1.0f : 0.0f;
    }

    // ---- Phase 3: re-read 84 channels (L2-hot for c<80), scale, stream out ----
    const int gh = by * TR + r;
    const int gx = bx * (TC / 2) + lane;
    const size_t pix2 = bbase2 + (size_t)gh * (WW / 2) + gx;
    const float2* src = pts2 + pix2;
    float2*       dst = out2 + pix2;
    #pragma unroll 4
    for (int c = 0; c < CC; ++c) {
        float2 v = __ldcs(src + (size_t)c * (HW / 2));   // last touch: evict-first
        v.x *= f.x;
        v.y *= f.y;
        __stcs(dst + (size_t)c * (HW / 2), v);           // streaming store
    }
}

// ---------------------------------------------------------------------------
extern "C" void kernel_launch(void* const* d_in, const int* in_sizes, int n_in,
                              void* d_out, int out_size) {
    const float2* pts = (const float2*)d_in[0];
    float2*       out = (float2*)d_out;

    dim3 grid(WW / TC, HH / TR, BB);   // (8, 64, 4) = 2048 CTAs
    fused_nms_kernel<<<grid, NT>>>(pts, out);
}